// round 2
// baseline (speedup 1.0000x reference)
#include <cuda_runtime.h>
#include <cuda_bf16.h>
#include <cfloat>
#include <cstdint>

// Problem constants
#define BATCH 32
#define DIM   256
#define HH    32
#define WW    32
#define HW    (HH*WW)              // 1024
#define NTOK  (BATCH*HW)           // 32768
#define KCODE 1024
#define NELEM ((size_t)BATCH*DIM*HW)  // 8388608

// Tiling for the distance/argmin kernel
#define TILE_T 64
#define TILE_K 64
#define DCH    16
#define NTHREADS 256

// -------- device scratch (no allocations allowed) --------
__device__ float  g_t1[NTOK];     // per-token sum z^2
__device__ float  g_s[KCODE];     // per-code  sum e^2
__device__ int    g_idx[NTOK];    // argmin index per token
__device__ double g_losssum;      // sum of (q-z)^2

// ============================================================
// Kernel A: prep — t1 per token, s per code, zero loss accum
// ============================================================
__global__ void vq_prep_kernel(const float* __restrict__ z,
                               const float* __restrict__ emb)
{
    int tid = blockIdx.x * blockDim.x + threadIdx.x;
    if (tid == 0) g_losssum = 0.0;

    if (tid < NTOK) {
        int b  = tid / HW;
        int hw = tid % HW;
        const float* base = z + (size_t)b * DIM * HW + hw;
        float s = 0.0f;
        #pragma unroll 8
        for (int d = 0; d < DIM; d++) {
            float v = base[(size_t)d * HW];
            s += v * v;                      // sequential fp32, ascending d
        }
        g_t1[tid] = s;
    } else if (tid < NTOK + KCODE) {
        int k = tid - NTOK;
        const float* row = emb + (size_t)k * DIM;
        float s = 0.0f;
        #pragma unroll 8
        for (int d = 0; d < DIM; d++) {
            float v = row[d];
            s += v * v;
        }
        g_s[k] = s;
    }
}

// ============================================================
// Kernel B: fused distance GEMM + argmin
//   block: 64 tokens x all 1024 codes (k-tiles of 64)
//   thread (tx=tid%16, ty=tid/16) owns 4 tokens x 4 codes
// ============================================================
__global__ __launch_bounds__(NTHREADS)
void vq_argmin_kernel(const float* __restrict__ z,
                      const float* __restrict__ emb)
{
    __shared__ float zs[DCH][TILE_T];   // [16][64]
    __shared__ float es[DCH][TILE_K];   // [16][64]
    __shared__ float red_v[TILE_T][16];
    __shared__ int   red_i[TILE_T][16];

    const int tid = threadIdx.x;
    const int tx  = tid & 15;    // code sub-tile
    const int ty  = tid >> 4;    // token sub-tile

    const int t0  = blockIdx.x * TILE_T;
    const int b   = t0 / HW;
    const int hw0 = t0 % HW;     // TILE_T divides HW, so tiles never cross b
    const float* zbase = z + (size_t)b * DIM * HW + hw0;

    float minv[4];
    int   mini[4];
    float t1r[4];
    #pragma unroll
    for (int i = 0; i < 4; i++) {
        minv[i] = FLT_MAX;
        mini[i] = 0;
        t1r[i]  = g_t1[t0 + 4 * ty + i];
    }

    for (int k0 = 0; k0 < KCODE; k0 += TILE_K) {
        float acc[4][4];
        #pragma unroll
        for (int i = 0; i < 4; i++)
            #pragma unroll
            for (int j = 0; j < 4; j++) acc[i][j] = 0.0f;

        for (int d0 = 0; d0 < DIM; d0 += DCH) {
            __syncthreads();   // protect previous iteration's smem reads

            // load z tile: zs[dd][tt] = z[b, d0+dd, hw0+tt]  (coalesced in tt)
            #pragma unroll
            for (int l = tid; l < DCH * TILE_T; l += NTHREADS) {
                int dd = l >> 6;          // /64
                int tt = l & 63;
                zs[dd][tt] = zbase[(size_t)(d0 + dd) * HW + tt];
            }
            // load e tile: es[dd][kk] = emb[k0+kk, d0+dd]  (float4 along d)
            {
                int c  = tid & 3;         // which float4 chunk of the 16 dims
                int kk = tid >> 2;        // 0..63
                const float4 ev = *(const float4*)(emb + (size_t)(k0 + kk) * DIM + d0 + 4 * c);
                es[4 * c + 0][kk] = ev.x;
                es[4 * c + 1][kk] = ev.y;
                es[4 * c + 2][kk] = ev.z;
                es[4 * c + 3][kk] = ev.w;
            }
            __syncthreads();

            #pragma unroll
            for (int dd = 0; dd < DCH; dd++) {
                const float4 zv = *(const float4*)&zs[dd][4 * ty];
                const float4 ev = *(const float4*)&es[dd][4 * tx];
                const float zr[4] = { zv.x, zv.y, zv.z, zv.w };
                const float er[4] = { ev.x, ev.y, ev.z, ev.w };
                #pragma unroll
                for (int i = 0; i < 4; i++)
                    #pragma unroll
                    for (int j = 0; j < 4; j++)
                        acc[i][j] = fmaf(zr[i], er[j], acc[i][j]);
            }
        }

        // distances for this k-tile, replicating reference rounding:
        // d = fl( fl(t1 - 2*m) + s_k )
        float sreg[4];
        #pragma unroll
        for (int j = 0; j < 4; j++) sreg[j] = g_s[k0 + 4 * tx + j];

        #pragma unroll
        for (int i = 0; i < 4; i++) {
            #pragma unroll
            for (int j = 0; j < 4; j++) {
                float dist = (t1r[i] - 2.0f * acc[i][j]) + sreg[j];
                int   kidx = k0 + 4 * tx + j;
                if (dist < minv[i]) { minv[i] = dist; mini[i] = kidx; }
                // strict < keeps the lowest index on exact ties (ascending k scan)
            }
        }
    }

    // cross-thread argmin reduce per token (tie -> lowest index)
    __syncthreads();
    #pragma unroll
    for (int i = 0; i < 4; i++) {
        red_v[4 * ty + i][tx] = minv[i];
        red_i[4 * ty + i][tx] = mini[i];
    }
    __syncthreads();
    if (tid < TILE_T) {
        float bv = red_v[tid][0];
        int   bi = red_i[tid][0];
        #pragma unroll
        for (int x = 1; x < 16; x++) {
            float v  = red_v[tid][x];
            int   ii = red_i[tid][x];
            if (v < bv || (v == bv && ii < bi)) { bv = v; bi = ii; }
        }
        g_idx[t0 + tid] = bi;
    }
}

// ============================================================
// Kernel C: output write (straight-through, bit-matching
//   out = z + (q - z)) and loss accumulation sum (q-z)^2
// ============================================================
__global__ __launch_bounds__(256)
void vq_out_kernel(const float* __restrict__ z,
                   const float* __restrict__ emb,
                   float* __restrict__ out)
{
    size_t i = (size_t)blockIdx.x * blockDim.x + threadIdx.x;  // < NELEM
    int hw = (int)(i & 1023);
    int d  = (int)((i >> 10) & 255);
    int b  = (int)(i >> 18);
    int t  = b * HW + hw;

    int   k    = g_idx[t];
    float zv   = z[i];
    float q    = emb[(size_t)k * DIM + d];
    float diff = q - zv;          // fl(q - z)
    out[i] = zv + diff;           // fl(z + fl(q - z))  == reference expression

    // block-reduced double accumulation of diff^2
    double v = (double)diff * (double)diff;
    #pragma unroll
    for (int o = 16; o > 0; o >>= 1)
        v += __shfl_down_sync(0xffffffffu, v, o);

    __shared__ double ws[8];
    int lane = threadIdx.x & 31;
    int wid  = threadIdx.x >> 5;
    if (lane == 0) ws[wid] = v;
    __syncthreads();
    if (threadIdx.x == 0) {
        double s = 0.0;
        #pragma unroll
        for (int w = 0; w < 8; w++) s += ws[w];
        atomicAdd(&g_losssum, s);
    }
}

// ============================================================
// Kernel D: finalize loss scalar
//   loss = m + 0.25f*m  with  m = fl(mean)
// ============================================================
__global__ void vq_loss_kernel(float* __restrict__ out, size_t loss_pos)
{
    if (threadIdx.x == 0 && blockIdx.x == 0) {
        float m = (float)(g_losssum / (double)NELEM);
        out[loss_pos] = m + 0.25f * m;
    }
}

// ============================================================
extern "C" void kernel_launch(void* const* d_in, const int* in_sizes, int n_in,
                              void* d_out, int out_size)
{
    const float* z;
    const float* emb;
    if (in_sizes[0] == (int)NELEM) {
        z = (const float*)d_in[0];
        emb = (const float*)d_in[1];
    } else {
        z = (const float*)d_in[1];
        emb = (const float*)d_in[0];
    }
    float* out = (float*)d_out;

    // A: prep (t1, s, zero loss)
    {
        int total = NTOK + KCODE;
        vq_prep_kernel<<<(total + 255) / 256, 256>>>(z, emb);
    }
    // B: fused distance + argmin
    {
        int blocks = NTOK / TILE_T;   // 512
        vq_argmin_kernel<<<blocks, NTHREADS>>>(z, emb);
    }
    // C: output + loss accumulation
    {
        int blocks = (int)(NELEM / 256);   // 32768
        vq_out_kernel<<<blocks, 256>>>(z, emb, out);
    }
    // D: loss scalar (last output element)
    {
        size_t loss_pos = (size_t)out_size - 1;
        vq_loss_kernel<<<1, 32>>>(out, loss_pos);
    }
}